// round 5
// baseline (speedup 1.0000x reference)
#include <cuda_runtime.h>
#include <cstdint>

// ============================================================================
// GaussianMLP fused — sm_103 plain target, mma.sync m16n8k8 tf32.
// R5: 64-row CTA tiles, 256 thr (8 warps, 2Mx4N), SMEM ~107KB -> 2 CTAs/SM.
//     K=16 double-buffered cp.async weight staging; register-direct epilogue.
// ============================================================================

#define NTILES 8192          // 64-row tiles

__device__ __forceinline__ uint32_t smem_u32(const void* p) {
    uint32_t a;
    asm("{ .reg .u64 t; cvta.to.shared.u64 t, %1; cvt.u32.u64 %0, t; }" : "=r"(a) : "l"(p));
    return a;
}
__device__ __forceinline__ float rna_tf32(float x) {
    float r;
    asm("cvt.rna.tf32.f32 %0, %1;" : "=f"(r) : "f"(x));
    return r;
}
__device__ __forceinline__ void mma8(float* c, const uint32_t* a, uint32_t b0, uint32_t b1) {
    asm volatile(
        "mma.sync.aligned.m16n8k8.row.col.f32.tf32.tf32.f32 "
        "{%0,%1,%2,%3},{%4,%5,%6,%7},{%8,%9},{%0,%1,%2,%3};"
        : "+f"(c[0]), "+f"(c[1]), "+f"(c[2]), "+f"(c[3])
        : "r"(a[0]), "r"(a[1]), "r"(a[2]), "r"(a[3]), "r"(b0), "r"(b1));
}
__device__ __forceinline__ void ldsm4(uint32_t* r, uint32_t addr) {
    asm volatile("ldmatrix.sync.aligned.m8n8.x4.shared.b16 {%0,%1,%2,%3}, [%4];"
                 : "=r"(r[0]), "=r"(r[1]), "=r"(r[2]), "=r"(r[3]) : "r"(addr));
}
#define CP16(dst, src) \
    asm volatile("cp.async.ca.shared.global [%0], [%1], 16;" :: "r"(dst), "l"(src))
#define CP_COMMIT() asm volatile("cp.async.commit_group;" ::: "memory")
#define CP_WAIT1()  asm volatile("cp.async.wait_group 1;" ::: "memory")
#define CP_WAIT0()  asm volatile("cp.async.wait_group 0;" ::: "memory")

// ---------------- pre-rounded, pre-transposed weights ------------------------
__device__ __align__(16) float g_wemb_t[256 * 128];   // [n][k]
__device__ __align__(16) float g_w2_t[256 * 256];     // [n][k]  n<128: Wm, else Wl

__global__ void prep_kernel(const float* __restrict__ We,
                            const float* __restrict__ Wm,
                            const float* __restrict__ Wl) {
    int i = blockIdx.x * 256 + threadIdx.x;
    if (i < 32768) {
        int n = i >> 7, k = i & 127;
        g_wemb_t[i] = rna_tf32(We[k * 256 + n]);
    } else if (i < 98304) {
        int j = i - 32768;
        int n = j >> 8, k = j & 255;
        float v = (n < 128) ? Wm[k * 128 + n] : Wl[k * 128 + (n - 128)];
        g_w2_t[j] = rna_tf32(v);
    }
}

// ---------------- SMEM map (per CTA, 109568 B) -------------------------------
// hs : h tile [64][260]                 66560   (xs bufs overlaid during L1;
//                                               reused as logvar tile in epi)
// wb : 2 x [256][20] weight stage bufs  40960
// bias                                   2048
#define HS_OFF   0u
#define XS0_OFF  0u
#define XS1_OFF  5120u
#define WB0_OFF  66560u
#define WB1_OFF  87040u
#define SBE_OFF  107520u
#define SBM_OFF  108544u
#define SBL_OFF  109056u
#define SMEM_TOTAL 109568
#define HS_S 260
#define XW_S 20           // K=16 chunk row stride (floats): 16 + 4 pad
#define MS_S 132

__global__ void __launch_bounds__(256, 2)
gauss_kernel(const float* __restrict__ x, const float* __restrict__ eps,
             const float* __restrict__ be, const float* __restrict__ bm,
             const float* __restrict__ bl, float* __restrict__ out) {
    extern __shared__ char smem[];
    const uint32_t sm = smem_u32(smem);
    float* hs  = (float*)(smem + HS_OFF);
    float* sbe = (float*)(smem + SBE_OFF);
    float* sbm = (float*)(smem + SBM_OFF);
    float* sbl = (float*)(smem + SBL_OFF);

    const int tid  = threadIdx.x;
    const int wid  = tid >> 5, lane = tid & 31;
    const int g    = lane >> 2, tg = lane & 3;
    const int mw   = wid & 1;                 // M block: 32 rows of 64
    const int nw   = wid >> 1;                // N block: 64 cols of 256
    const int nb   = nw * 64;
    const size_t tile = blockIdx.x;

    // ldmatrix lane address components
    const int a_row  = (lane & 7) + ((lane & 8) ? 8 : 0);
    const int a_koff = (lane & 16) ? 4 : 0;
    const int b_n    = (lane & 7) + ((lane & 16) ? 8 : 0);
    const int b_koff = (lane & 8) ? 4 : 0;

    sbe[tid] = be[tid];
    if (tid < 128) { sbm[tid] = bm[tid]; sbl[tid] = bl[tid]; }

    const float* xg = x + tile * 8192;        // 64 rows x 128
    const int s_row = tid >> 2, s_q = tid & 3;   // 64 rows x 4 quads

    // stage one K=16 weight chunk: [256 n][16 k]
    auto issue_w = [&](const float* src, int sstride, int kbase, uint32_t dstbase) {
        #pragma unroll
        for (int j = 0; j < 4; j++) {
            int row = s_row + j * 64;
            const float* gp = src + row * sstride + kbase + s_q * 4;
            uint32_t sa = dstbase + (uint32_t)(row * XW_S + s_q * 4) * 4u;
            CP16(sa, gp);
        }
    };
    // stage one K=16 x chunk: [64 rows][16 k]
    auto issue_x = [&](int ks, uint32_t dstbase) {
        const float* gp = xg + s_row * 128 + ks * 16 + s_q * 4;
        uint32_t sa = dstbase + (uint32_t)(s_row * XW_S + s_q * 4) * 4u;
        CP16(sa, gp);
    };

    const uint32_t xsb[2] = { sm + XS0_OFF, sm + XS1_OFF };
    const uint32_t wbb[2] = { sm + WB0_OFF, sm + WB1_OFF };

    float acc[2][8][4];
    #pragma unroll
    for (int m = 0; m < 2; m++)
        #pragma unroll
        for (int n = 0; n < 8; n++)
            #pragma unroll
            for (int c = 0; c < 4; c++) acc[m][n][c] = 0.0f;

    issue_x(0, xsb[0]);
    issue_w(g_wemb_t, 128, 0, wbb[0]);
    CP_COMMIT();

    // ======================= layer 1 (8 stages of K=16) ======================
    #pragma unroll 1
    for (int s = 0; s < 8; s++) {
        const int cur = s & 1, nxt = cur ^ 1;
        __syncthreads();                       // prev compute reads of nxt done
        if (s < 7) {
            issue_x(s + 1, xsb[nxt]);
            issue_w(g_wemb_t, 128, (s + 1) * 16, wbb[nxt]);
            CP_COMMIT(); CP_WAIT1();
        } else {
            issue_w(g_w2_t, 256, 0, wbb[nxt]); // prefetch layer-2 chunk 0
            CP_COMMIT(); CP_WAIT1();
        }
        __syncthreads();                       // cur buffers visible

        const uint32_t a0 = xsb[cur] + (uint32_t)((mw * 32 + a_row) * XW_S + a_koff) * 4u;
        const uint32_t b0 = wbb[cur] + (uint32_t)((nb + b_n) * XW_S + b_koff) * 4u;
        #pragma unroll
        for (int kk = 0; kk < 2; kk++) {
            uint32_t A[2][4];
            #pragma unroll
            for (int m = 0; m < 2; m++) {
                ldsm4(A[m], a0 + (uint32_t)(m * 16 * XW_S) * 4u + kk * 32u);
                #pragma unroll
                for (int c = 0; c < 4; c++)
                    A[m][c] = __float_as_uint(rna_tf32(__uint_as_float(A[m][c])));
            }
            #pragma unroll
            for (int p = 0; p < 4; p++) {
                uint32_t B[4];
                ldsm4(B, b0 + (uint32_t)(p * 16 * XW_S) * 4u + kk * 32u);
                #pragma unroll
                for (int m = 0; m < 2; m++) {
                    mma8(acc[m][2 * p],     A[m], B[0], B[1]);
                    mma8(acc[m][2 * p + 1], A[m], B[2], B[3]);
                }
            }
        }
    }

    // ---- h = tf32(relu(acc + b_emb)) -> SMEM (xs region now dead) ----
    __syncthreads();
    {
        #pragma unroll
        for (int m = 0; m < 2; m++) {
            const int r0 = mw * 32 + m * 16 + g;
            #pragma unroll
            for (int n = 0; n < 8; n++) {
                int col = nb + n * 8 + 2 * tg;
                float b0v = sbe[col], b1v = sbe[col + 1];
                float2 v0, v1;
                v0.x = rna_tf32(fmaxf(acc[m][n][0] + b0v, 0.0f));
                v0.y = rna_tf32(fmaxf(acc[m][n][1] + b1v, 0.0f));
                v1.x = rna_tf32(fmaxf(acc[m][n][2] + b0v, 0.0f));
                v1.y = rna_tf32(fmaxf(acc[m][n][3] + b1v, 0.0f));
                *(float2*)&hs[r0 * HS_S + col]       = v0;
                *(float2*)&hs[(r0 + 8) * HS_S + col] = v1;
            }
        }
    }

    #pragma unroll
    for (int m = 0; m < 2; m++)
        #pragma unroll
        for (int n = 0; n < 8; n++)
            #pragma unroll
            for (int c = 0; c < 4; c++) acc[m][n][c] = 0.0f;

    // ======================= layer 2 (16 chunks of K=16) =====================
    #pragma unroll 1
    for (int c16 = 0; c16 < 16; c16++) {
        const int cur = c16 & 1, nxt = cur ^ 1;
        __syncthreads();                       // h visible (c16=0) / prev reads done
        if (c16 < 15) { issue_w(g_w2_t, 256, (c16 + 1) * 16, wbb[nxt]); CP_COMMIT(); CP_WAIT1(); }
        else          { CP_WAIT0(); }
        __syncthreads();

        const uint32_t a0 = sm + HS_OFF
            + (uint32_t)((mw * 32 + a_row) * HS_S + c16 * 16 + a_koff) * 4u;
        const uint32_t b0 = wbb[cur] + (uint32_t)((nb + b_n) * XW_S + b_koff) * 4u;
        #pragma unroll
        for (int kk = 0; kk < 2; kk++) {
            uint32_t A[2][4];
            #pragma unroll
            for (int m = 0; m < 2; m++)
                ldsm4(A[m], a0 + (uint32_t)(m * 16 * HS_S) * 4u + kk * 32u);
            #pragma unroll
            for (int p = 0; p < 4; p++) {
                uint32_t B[4];
                ldsm4(B, b0 + (uint32_t)(p * 16 * XW_S) * 4u + kk * 32u);
                #pragma unroll
                for (int m = 0; m < 2; m++) {
                    mma8(acc[m][2 * p],     A[m], B[0], B[1]);
                    mma8(acc[m][2 * p + 1], A[m], B[2], B[3]);
                }
            }
        }
    }
    __syncthreads();   // hs reads complete — reuse region for logvar exchange

    // ============== epilogue: register-direct, fragment layout ===============
    // warps nw>=2 own logvar (cols 128..255): bias, store gmem + SMEM tile.
    if (nw >= 2) {
        float* ls = (float*)smem;              // [64][MS_S]
        const int cb2 = nb - 128;
        float* olg = out + 134217728u + tile * 8192;
        #pragma unroll
        for (int m = 0; m < 2; m++) {
            const int rA = mw * 32 + m * 16 + g, rB = rA + 8;
            #pragma unroll
            for (int n = 0; n < 8; n++) {
                int cc = cb2 + n * 8 + 2 * tg;
                float b0v = sbl[cc], b1v = sbl[cc + 1];
                float2 v0 = make_float2(acc[m][n][0] + b0v, acc[m][n][1] + b1v);
                float2 v1 = make_float2(acc[m][n][2] + b0v, acc[m][n][3] + b1v);
                *(float2*)&ls[rA * MS_S + cc] = v0;
                *(float2*)&ls[rB * MS_S + cc] = v1;
                *(float2*)&olg[rA * 128 + cc] = v0;
                *(float2*)&olg[rB * 128 + cc] = v1;
            }
        }
    }
    __syncthreads();
    // warps nw<2 own mean (cols 0..127): read logvar tile, compute z.
    if (nw < 2) {
        const float* ls = (const float*)smem;
        const float* eg = eps + tile * 8192;
        float* oz = out + tile * 8192;
        float* om = out + 67108864u + tile * 8192;
        #pragma unroll
        for (int m = 0; m < 2; m++) {
            const int rA = mw * 32 + m * 16 + g, rB = rA + 8;
            #pragma unroll
            for (int n = 0; n < 8; n++) {
                int cc = nb + n * 8 + 2 * tg;
                float b0v = sbm[cc], b1v = sbm[cc + 1];
                float2 m0 = make_float2(acc[m][n][0] + b0v, acc[m][n][1] + b1v);
                float2 m1 = make_float2(acc[m][n][2] + b0v, acc[m][n][3] + b1v);
                float2 l0 = *(const float2*)&ls[rA * MS_S + cc];
                float2 l1 = *(const float2*)&ls[rB * MS_S + cc];
                float2 e0 = *(const float2*)&eg[rA * 128 + cc];
                float2 e1 = *(const float2*)&eg[rB * 128 + cc];
                float2 z0, z1;
                z0.x = fmaf(__expf(0.5f * l0.x), e0.x, m0.x);
                z0.y = fmaf(__expf(0.5f * l0.y), e0.y, m0.y);
                z1.x = fmaf(__expf(0.5f * l1.x), e1.x, m1.x);
                z1.y = fmaf(__expf(0.5f * l1.y), e1.y, m1.y);
                *(float2*)&oz[rA * 128 + cc] = z0;
                *(float2*)&oz[rB * 128 + cc] = z1;
                *(float2*)&om[rA * 128 + cc] = m0;
                *(float2*)&om[rB * 128 + cc] = m1;
            }
        }
    }
}

// ---------------------------------------------------------------------------

extern "C" void kernel_launch(void* const* d_in, const int* in_sizes, int n_in,
                              void* d_out, int out_size) {
    const float* x   = (const float*)d_in[0];
    const float* eps = (const float*)d_in[1];
    const float* We  = (const float*)d_in[2];
    const float* be  = (const float*)d_in[3];
    const float* Wm  = (const float*)d_in[4];
    const float* bm  = (const float*)d_in[5];
    const float* Wl  = (const float*)d_in[6];
    const float* bl  = (const float*)d_in[7];
    float* out = (float*)d_out;

    cudaFuncSetAttribute(gauss_kernel, cudaFuncAttributeMaxDynamicSharedMemorySize, SMEM_TOTAL);
    prep_kernel<<<384, 256>>>(We, Wm, Wl);
    gauss_kernel<<<NTILES, 256, SMEM_TOTAL>>>(x, eps, be, bm, bl, out);
}

// round 6
// speedup vs baseline: 1.2493x; 1.2493x over previous
#include <cuda_runtime.h>
#include <cstdint>

// ============================================================================
// GaussianMLP fused — sm_103 plain target, mma.sync m16n8k8 tf32.
// R6: 128-row tiles, 512 thr (4x4 warps, M32xN64), K=16 chunks in a 3-slot
//     cp.async ring, SINGLE __syncthreads per stage, cg (L1-bypass) staging.
// ============================================================================

#define NTILES 4096

__device__ __forceinline__ uint32_t smem_u32(const void* p) {
    uint32_t a;
    asm("{ .reg .u64 t; cvta.to.shared.u64 t, %1; cvt.u32.u64 %0, t; }" : "=r"(a) : "l"(p));
    return a;
}
__device__ __forceinline__ float rna_tf32(float x) {
    float r;
    asm("cvt.rna.tf32.f32 %0, %1;" : "=f"(r) : "f"(x));
    return r;
}
__device__ __forceinline__ void mma8(float* c, const uint32_t* a, uint32_t b0, uint32_t b1) {
    asm volatile(
        "mma.sync.aligned.m16n8k8.row.col.f32.tf32.tf32.f32 "
        "{%0,%1,%2,%3},{%4,%5,%6,%7},{%8,%9},{%0,%1,%2,%3};"
        : "+f"(c[0]), "+f"(c[1]), "+f"(c[2]), "+f"(c[3])
        : "r"(a[0]), "r"(a[1]), "r"(a[2]), "r"(a[3]), "r"(b0), "r"(b1));
}
__device__ __forceinline__ void ldsm4(uint32_t* r, uint32_t addr) {
    asm volatile("ldmatrix.sync.aligned.m8n8.x4.shared.b16 {%0,%1,%2,%3}, [%4];"
                 : "=r"(r[0]), "=r"(r[1]), "=r"(r[2]), "=r"(r[3]) : "r"(addr));
}
#define CP16CG(dst, src) \
    asm volatile("cp.async.cg.shared.global [%0], [%1], 16;" :: "r"(dst), "l"(src))
#define CP_COMMIT() asm volatile("cp.async.commit_group;" ::: "memory")
#define CP_WAIT1()  asm volatile("cp.async.wait_group 1;" ::: "memory")
#define CP_WAIT0()  asm volatile("cp.async.wait_group 0;" ::: "memory")

// ---------------- pre-rounded, pre-transposed weights ------------------------
__device__ __align__(16) float g_wemb_t[256 * 128];   // [n][k]
__device__ __align__(16) float g_w2_t[256 * 256];     // [n][k]  n<128: Wm, else Wl

__global__ void prep_kernel(const float* __restrict__ We,
                            const float* __restrict__ Wm,
                            const float* __restrict__ Wl) {
    int i = blockIdx.x * 256 + threadIdx.x;
    if (i < 32768) {
        int n = i >> 7, k = i & 127;
        g_wemb_t[i] = rna_tf32(We[k * 256 + n]);
    } else if (i < 98304) {
        int j = i - 32768;
        int n = j >> 8, k = j & 255;
        float v = (n < 128) ? Wm[k * 128 + n] : Wl[k * 128 + (n - 128)];
        g_w2_t[j] = rna_tf32(v);
    }
}

// ---------------- SMEM map (227328 B) ----------------------------------------
// hs   : h tile [128][260]                    133120  (logvar exchange in epi)
// ring : 3 slots x 30720  (W [256][20] @ +0, X [128][20] @ +20480)
// bias : 2048
#define HS_OFF    0u
#define RING_OFF  133120u
#define SLOT_SZ   30720u
#define XOFF_IN_SLOT 20480u
#define SBE_OFF   225280u
#define SBM_OFF   226304u
#define SBL_OFF   226816u
#define SMEM_TOTAL 227328
#define HS_S 260
#define XW_S 20
#define MS_S 132

__global__ void __launch_bounds__(512, 1)
gauss_kernel(const float* __restrict__ x, const float* __restrict__ eps,
             const float* __restrict__ be, const float* __restrict__ bm,
             const float* __restrict__ bl, float* __restrict__ out) {
    extern __shared__ char smem[];
    const uint32_t sm = smem_u32(smem);
    float* hs  = (float*)(smem + HS_OFF);
    float* sbe = (float*)(smem + SBE_OFF);
    float* sbm = (float*)(smem + SBM_OFF);
    float* sbl = (float*)(smem + SBL_OFF);

    const int tid  = threadIdx.x;
    const int wid  = tid >> 5, lane = tid & 31;
    const int g    = lane >> 2, tg = lane & 3;
    const int mw   = wid & 3;                 // M block (32 rows)
    const int nw   = wid >> 2;                // N block (64 cols)
    const int nb   = nw * 64;
    const size_t tile = blockIdx.x;

    const int a_row  = (lane & 7) + ((lane & 8) ? 8 : 0);
    const int a_koff = (lane & 16) ? 4 : 0;
    const int b_n    = (lane & 7) + ((lane & 16) ? 8 : 0);
    const int b_koff = (lane & 8) ? 4 : 0;

    if (tid < 256) sbe[tid] = be[tid];
    if (tid < 128) { sbm[tid] = bm[tid]; sbl[tid] = bl[tid]; }

    const float* xg = x + tile * 16384;
    const int s_row = tid >> 2, s_q = tid & 3;        // 128 rows x 4 quads

    // ---- stage issue: stage i -> slot i%3 -----------------------------------
    auto slot_base = [&](int i) -> uint32_t {
        return sm + RING_OFF + (uint32_t)(i % 3) * SLOT_SZ;
    };
    auto issue_stage = [&](int i) {
        uint32_t base = slot_base(i);
        if (i < 8) {
            // W_emb chunk [256 n][16 k] + x chunk [128 r][16 k]
            const float* w = g_wemb_t + i * 16;
            #pragma unroll
            for (int j = 0; j < 2; j++) {
                int row = s_row + j * 128;
                CP16CG(base + (uint32_t)(row * XW_S + s_q * 4) * 4u,
                       w + row * 128 + s_q * 4);
            }
            CP16CG(base + XOFF_IN_SLOT + (uint32_t)(s_row * XW_S + s_q * 4) * 4u,
                   xg + s_row * 128 + i * 16 + s_q * 4);
        } else {
            const float* w = g_w2_t + (i - 8) * 16;
            #pragma unroll
            for (int j = 0; j < 2; j++) {
                int row = s_row + j * 128;
                CP16CG(base + (uint32_t)(row * XW_S + s_q * 4) * 4u,
                       w + row * 256 + s_q * 4);
            }
        }
        CP_COMMIT();
    };

    float acc[2][8][4];
    #pragma unroll
    for (int m = 0; m < 2; m++)
        #pragma unroll
        for (int n = 0; n < 8; n++)
            #pragma unroll
            for (int c = 0; c < 4; c++) acc[m][n][c] = 0.0f;

    // prologue: stages 0,1 in flight
    issue_stage(0);
    issue_stage(1);

    // ======================= layer 1 (stages 0..7) ===========================
    #pragma unroll 1
    for (int s = 0; s < 8; s++) {
        CP_WAIT1();                 // this thread's stage-s group done
        __syncthreads();            // everyone's stage-s visible; slot s-1 reads done
        issue_stage(s + 2);         // into slot (s-1)%3

        const uint32_t base = slot_base(s);
        const uint32_t a0 = base + XOFF_IN_SLOT
            + (uint32_t)((mw * 32 + a_row) * XW_S + a_koff) * 4u;
        const uint32_t b0 = base + (uint32_t)((nb + b_n) * XW_S + b_koff) * 4u;
        #pragma unroll
        for (int kk = 0; kk < 2; kk++) {
            uint32_t A[2][4];
            #pragma unroll
            for (int m = 0; m < 2; m++) {
                ldsm4(A[m], a0 + (uint32_t)(m * 16 * XW_S) * 4u + kk * 32u);
                #pragma unroll
                for (int c = 0; c < 4; c++)
                    A[m][c] = __float_as_uint(rna_tf32(__uint_as_float(A[m][c])));
            }
            #pragma unroll
            for (int p = 0; p < 4; p++) {
                uint32_t B[4];
                ldsm4(B, b0 + (uint32_t)(p * 16 * XW_S) * 4u + kk * 32u);
                #pragma unroll
                for (int m = 0; m < 2; m++) {
                    mma8(acc[m][2 * p],     A[m], B[0], B[1]);
                    mma8(acc[m][2 * p + 1], A[m], B[2], B[3]);
                }
            }
        }
    }

    // ---- h = tf32(relu(acc + b_emb)) -> SMEM (hs region, no ring overlap) ---
    {
        #pragma unroll
        for (int m = 0; m < 2; m++) {
            const int r0 = mw * 32 + m * 16 + g;
            #pragma unroll
            for (int n = 0; n < 8; n++) {
                int col = nb + n * 8 + 2 * tg;
                float b0v = sbe[col], b1v = sbe[col + 1];
                float2 v0, v1;
                v0.x = rna_tf32(fmaxf(acc[m][n][0] + b0v, 0.0f));
                v0.y = rna_tf32(fmaxf(acc[m][n][1] + b1v, 0.0f));
                v1.x = rna_tf32(fmaxf(acc[m][n][2] + b0v, 0.0f));
                v1.y = rna_tf32(fmaxf(acc[m][n][3] + b1v, 0.0f));
                *(float2*)&hs[r0 * HS_S + col]       = v0;
                *(float2*)&hs[(r0 + 8) * HS_S + col] = v1;
            }
        }
    }
    #pragma unroll
    for (int m = 0; m < 2; m++)
        #pragma unroll
        for (int n = 0; n < 8; n++)
            #pragma unroll
            for (int c = 0; c < 4; c++) acc[m][n][c] = 0.0f;

    // ======================= layer 2 (stages 8..23) ==========================
    #pragma unroll 1
    for (int i = 8; i < 24; i++) {
        if (i == 23) { CP_WAIT0(); } else { CP_WAIT1(); }
        __syncthreads();            // stage-i visible; also gates h writes (i==8)
        if (i + 2 < 24) issue_stage(i + 2);

        const int c16 = i - 8;
        const uint32_t b0 = slot_base(i) + (uint32_t)((nb + b_n) * XW_S + b_koff) * 4u;
        const uint32_t a0 = sm + HS_OFF
            + (uint32_t)((mw * 32 + a_row) * HS_S + c16 * 16 + a_koff) * 4u;
        #pragma unroll
        for (int kk = 0; kk < 2; kk++) {
            uint32_t A[2][4];
            #pragma unroll
            for (int m = 0; m < 2; m++)
                ldsm4(A[m], a0 + (uint32_t)(m * 16 * HS_S) * 4u + kk * 32u);
            #pragma unroll
            for (int p = 0; p < 4; p++) {
                uint32_t B[4];
                ldsm4(B, b0 + (uint32_t)(p * 16 * XW_S) * 4u + kk * 32u);
                #pragma unroll
                for (int m = 0; m < 2; m++) {
                    mma8(acc[m][2 * p],     A[m], B[0], B[1]);
                    mma8(acc[m][2 * p + 1], A[m], B[2], B[3]);
                }
            }
        }
    }
    __syncthreads();   // hs reads complete — reuse region for logvar exchange

    // ============== epilogue: register-direct, fragment layout ===============
    if (nw >= 2) {     // logvar warps (cols 128..255)
        float* ls = (float*)smem;
        const int cb2 = nb - 128;
        float* olg = out + 134217728u + tile * 16384;
        #pragma unroll
        for (int m = 0; m < 2; m++) {
            const int rA = mw * 32 + m * 16 + g, rB = rA + 8;
            #pragma unroll
            for (int n = 0; n < 8; n++) {
                int cc = cb2 + n * 8 + 2 * tg;
                float b0v = sbl[cc], b1v = sbl[cc + 1];
                float2 v0 = make_float2(acc[m][n][0] + b0v, acc[m][n][1] + b1v);
                float2 v1 = make_float2(acc[m][n][2] + b0v, acc[m][n][3] + b1v);
                *(float2*)&ls[rA * MS_S + cc] = v0;
                *(float2*)&ls[rB * MS_S + cc] = v1;
                *(float2*)&olg[rA * 128 + cc] = v0;
                *(float2*)&olg[rB * 128 + cc] = v1;
            }
        }
    }
    __syncthreads();
    if (nw < 2) {      // mean warps (cols 0..127)
        const float* ls = (const float*)smem;
        const float* eg = eps + tile * 16384;
        float* oz = out + tile * 16384;
        float* om = out + 67108864u + tile * 16384;
        #pragma unroll
        for (int m = 0; m < 2; m++) {
            const int rA = mw * 32 + m * 16 + g, rB = rA + 8;
            #pragma unroll
            for (int n = 0; n < 8; n++) {
                int cc = nb + n * 8 + 2 * tg;
                float b0v = sbm[cc], b1v = sbm[cc + 1];
                float2 m0 = make_float2(acc[m][n][0] + b0v, acc[m][n][1] + b1v);
                float2 m1 = make_float2(acc[m][n][2] + b0v, acc[m][n][3] + b1v);
                float2 l0 = *(const float2*)&ls[rA * MS_S + cc];
                float2 l1 = *(const float2*)&ls[rB * MS_S + cc];
                float2 e0 = *(const float2*)&eg[rA * 128 + cc];
                float2 e1 = *(const float2*)&eg[rB * 128 + cc];
                float2 z0, z1;
                z0.x = fmaf(__expf(0.5f * l0.x), e0.x, m0.x);
                z0.y = fmaf(__expf(0.5f * l0.y), e0.y, m0.y);
                z1.x = fmaf(__expf(0.5f * l1.x), e1.x, m1.x);
                z1.y = fmaf(__expf(0.5f * l1.y), e1.y, m1.y);
                *(float2*)&oz[rA * 128 + cc] = z0;
                *(float2*)&oz[rB * 128 + cc] = z1;
                *(float2*)&om[rA * 128 + cc] = m0;
                *(float2*)&om[rB * 128 + cc] = m1;
            }
        }
    }
}

// ---------------------------------------------------------------------------

extern "C" void kernel_launch(void* const* d_in, const int* in_sizes, int n_in,
                              void* d_out, int out_size) {
    const float* x   = (const float*)d_in[0];
    const float* eps = (const float*)d_in[1];
    const float* We  = (const float*)d_in[2];
    const float* be  = (const float*)d_in[3];
    const float* Wm  = (const float*)d_in[4];
    const float* bm  = (const float*)d_in[5];
    const float* Wl  = (const float*)d_in[6];
    const float* bl  = (const float*)d_in[7];
    float* out = (float*)d_out;

    cudaFuncSetAttribute(gauss_kernel, cudaFuncAttributeMaxDynamicSharedMemorySize, SMEM_TOTAL);
    prep_kernel<<<384, 256>>>(We, Wm, Wl);
    gauss_kernel<<<NTILES, 512, SMEM_TOTAL>>>(x, eps, be, bm, bl, out);
}